// round 8
// baseline (speedup 1.0000x reference)
#include <cuda_runtime.h>

// Y: [16384, 2048] fp32, row-major.
// loss = sum_d | 1 - (sum_n Y[n,d]^2) / n |

#define N_ROWS         16384
#define N_COLS         2048
#define COLS4          (N_COLS / 4)              // 512 float4 per row
#define ROWS_PER_BLOCK 16
#define GRID1          (N_ROWS / ROWS_PER_BLOCK) // 1024 blocks

// Zero-initialized device global (no cudaMalloc allowed). finalize_kernel
// resets it after reading, so every graph replay starts clean.
__device__ float g_colsum[N_COLS];

// R1's proven streaming shape: 1024 small blocks -> fine-grained drain
// scheduling across 148 SMs (imbalance ~1 block of 16 rows), full occupancy,
// 16 front-batched LDG.128 per thread. Endgame: 4 REDG.ADD per thread into
// the 2048-entry column-sum array (staggered by block completion order).
__global__ __launch_bounds__(512) void colsq_kernel(const float4* __restrict__ Y)
{
    const int col4 = threadIdx.x;                       // 0..511
    const long base = (long)blockIdx.x * ROWS_PER_BLOCK * COLS4 + col4;

    float ax = 0.f, ay = 0.f, az = 0.f, aw = 0.f;
    #pragma unroll
    for (int r = 0; r < ROWS_PER_BLOCK; r++) {
        float4 v = Y[base + (long)r * COLS4];
        ax = fmaf(v.x, v.x, ax);
        ay = fmaf(v.y, v.y, ay);
        az = fmaf(v.z, v.z, az);
        aw = fmaf(v.w, v.w, aw);
    }

    const int c = col4 * 4;
    atomicAdd(&g_colsum[c + 0], ax);
    atomicAdd(&g_colsum[c + 1], ay);
    atomicAdd(&g_colsum[c + 2], az);
    atomicAdd(&g_colsum[c + 3], aw);
}

// Finalize: one block reads the 2048 column sums (8 KB, L2-hot), computes
// sum |1 - s/n|, writes the scalar, and resets state for the next replay.
__global__ __launch_bounds__(512) void finalize_kernel(float* __restrict__ out)
{
    const int t = threadIdx.x;                          // 0..511
    const float inv_n = 1.0f / (float)N_ROWS;

    float4 s = reinterpret_cast<const float4*>(g_colsum)[t];
    float v = fabsf(1.0f - s.x * inv_n) + fabsf(1.0f - s.y * inv_n)
            + fabsf(1.0f - s.z * inv_n) + fabsf(1.0f - s.w * inv_n);

    // Reset for the next graph replay.
    reinterpret_cast<float4*>(g_colsum)[t] = make_float4(0.f, 0.f, 0.f, 0.f);

    __shared__ float red[16];
    #pragma unroll
    for (int o = 16; o > 0; o >>= 1)
        v += __shfl_down_sync(0xffffffff, v, o);
    if ((t & 31) == 0) red[t >> 5] = v;
    __syncthreads();
    if (t < 16) {
        float x = red[t];
        #pragma unroll
        for (int o = 8; o > 0; o >>= 1)
            x += __shfl_down_sync(0xffff, x, o);
        if (t == 0) out[0] = x;
    }
}

extern "C" void kernel_launch(void* const* d_in, const int* in_sizes, int n_in,
                              void* d_out, int out_size)
{
    const float4* Y = (const float4*)d_in[0];
    float* out = (float*)d_out;

    colsq_kernel<<<GRID1, 512>>>(Y);
    finalize_kernel<<<1, 512>>>(out);
}

// round 9
// speedup vs baseline: 2.2803x; 2.2803x over previous
#include <cuda_runtime.h>

// Y: [16384, 2048] fp32, row-major.
// loss = sum_d | 1 - (sum_n Y[n,d]^2) / n |

#define N_ROWS   16384
#define N_COLS   2048
#define COLS4    (N_COLS / 4)        // 512 float4 per row
#define ROWS_PER_BLOCK 64
#define GRID1    (N_ROWS / ROWS_PER_BLOCK)   // 256 blocks

// Scratch: per-block partial column sums of squares, [GRID1][COLS4] float4 = 2 MB.
__device__ float4 g_partial[GRID1 * COLS4];

// K1: proven R3 streaming body (~5.9 TB/s). 256 blocks x 512 threads, each
// block owns a contiguous 64-row slab, fully unrolled -> 16 LDG.128 batches.
__global__ __launch_bounds__(COLS4) void colsq_kernel(
    const float4* __restrict__ Y, float* __restrict__ out)
{
    const int col4 = threadIdx.x;                       // 0..511
    const long base = (long)blockIdx.x * ROWS_PER_BLOCK * COLS4 + col4;

    float ax = 0.f, ay = 0.f, az = 0.f, aw = 0.f;
    #pragma unroll
    for (int r = 0; r < ROWS_PER_BLOCK; r += 4) {
        float4 v0 = Y[base + (long)(r + 0) * COLS4];
        float4 v1 = Y[base + (long)(r + 1) * COLS4];
        float4 v2 = Y[base + (long)(r + 2) * COLS4];
        float4 v3 = Y[base + (long)(r + 3) * COLS4];
        ax = fmaf(v0.x, v0.x, ax); ay = fmaf(v0.y, v0.y, ay);
        az = fmaf(v0.z, v0.z, az); aw = fmaf(v0.w, v0.w, aw);
        ax = fmaf(v1.x, v1.x, ax); ay = fmaf(v1.y, v1.y, ay);
        az = fmaf(v1.z, v1.z, az); aw = fmaf(v1.w, v1.w, aw);
        ax = fmaf(v2.x, v2.x, ax); ay = fmaf(v2.y, v2.y, ay);
        az = fmaf(v2.z, v2.z, az); aw = fmaf(v2.w, v2.w, aw);
        ax = fmaf(v3.x, v3.x, ax); ay = fmaf(v3.y, v3.y, ay);
        az = fmaf(v3.z, v3.z, az); aw = fmaf(v3.w, v3.w, aw);
    }
    float4 acc; acc.x = ax; acc.y = ay; acc.z = az; acc.w = aw;
    g_partial[(long)blockIdx.x * COLS4 + col4] = acc;

    // Zero the scalar output; K2 (same stream, after K1) atomically adds into it.
    if (blockIdx.x == 0 && threadIdx.x == 0) out[0] = 0.0f;
}

// K2: 128 blocks x 1024 threads, ONE float4 load per thread.
// Block b owns f4-columns [b*4, b*4+4). Thread t: fc = t&3, rg = t>>2
// covers all 256 partial rows in a single fully-parallel coalesced pass
// (within a warp: 4 adjacent f4cols x 8 rows -> clean 128B segments).
__global__ __launch_bounds__(1024) void reduce_kernel(float* __restrict__ out)
{
    const int t  = threadIdx.x;
    const int fc = t & 3;                    // f4-column within block's set
    const int rg = t >> 2;                   // partial row (0..255)
    const int f4col = blockIdx.x * 4 + fc;   // 0..511

    float4 a = g_partial[(long)rg * COLS4 + f4col];

    __shared__ float4 s[1024];               // index = rg*4 + fc == t
    s[t] = a;
    __syncthreads();

    // Tree-reduce over rg (256 -> 1) per fc.
    #pragma unroll
    for (int stride = 128; stride >= 1; stride >>= 1) {
        if (rg < stride) {
            float4 b2 = s[(rg + stride) * 4 + fc];
            float4 a2 = s[t];
            a2.x += b2.x; a2.y += b2.y; a2.z += b2.z; a2.w += b2.w;
            s[t] = a2;
        }
        __syncthreads();
    }

    // s[fc], fc in [0,4): column sums for this block's 16 scalar columns.
    if (t == 0) {
        const float inv_n = 1.0f / (float)N_ROWS;
        float total = 0.f;
        #pragma unroll
        for (int f = 0; f < 4; f++) {
            float4 d = s[f];
            total += fabsf(1.0f - d.x * inv_n);
            total += fabsf(1.0f - d.y * inv_n);
            total += fabsf(1.0f - d.z * inv_n);
            total += fabsf(1.0f - d.w * inv_n);
        }
        atomicAdd(out, total);
    }
}

extern "C" void kernel_launch(void* const* d_in, const int* in_sizes, int n_in,
                              void* d_out, int out_size)
{
    const float4* Y = (const float4*)d_in[0];
    float* out = (float*)d_out;

    colsq_kernel<<<GRID1, COLS4>>>(Y, out);
    reduce_kernel<<<128, 1024>>>(out);
}